// round 2
// baseline (speedup 1.0000x reference)
#include <cuda_runtime.h>
#include <cstdint>

#define NPOS  8192
#define NNEG  4096
#define NVIS  4096
#define DIM   64
#define MMEM  24576   // NPOS + 4*NNEG
#define NX    12288   // NPOS + NNEG

#define BM 128
#define BN 128

// ---------------- device scratch (no allocations allowed) ----------------
__device__ unsigned long long g_best[NPOS];
__device__ float g_cnt[NPOS];
__device__ float g_vis[NPOS];
__device__ float g_acc[NPOS * DIM];

// ---------------- helpers ----------------
__device__ __forceinline__ unsigned long long packv(float v, int col) {
    unsigned int u = __float_as_uint(v);
    u = (u & 0x80000000u) ? ~u : (u | 0x80000000u);  // monotone sortable key
    return ((unsigned long long)u << 32) | (unsigned int)(0xFFFFFFFFu - (unsigned int)col);
}

__device__ __forceinline__ void mma_tf32(float c[4], const unsigned int a[4], const unsigned int b[2]) {
    asm volatile(
        "mma.sync.aligned.m16n8k8.row.col.f32.tf32.tf32.f32 "
        "{%0,%1,%2,%3}, {%4,%5,%6,%7}, {%8,%9}, {%0,%1,%2,%3};\n"
        : "+f"(c[0]), "+f"(c[1]), "+f"(c[2]), "+f"(c[3])
        : "r"(a[0]), "r"(a[1]), "r"(a[2]), "r"(a[3]), "r"(b[0]), "r"(b[1]));
}

__device__ __forceinline__ void split_tf32(float x, unsigned int &hi, unsigned int &lo) {
    unsigned int ub = __float_as_uint(x);
    unsigned int hb = ub & 0xFFFFE000u;          // truncate to tf32 (exact split)
    hi = hb;
    lo = __float_as_uint(x - __uint_as_float(hb)); // exact residual; HW truncates to tf32
}

// ---------------- kernels ----------------
__global__ void k_init() {
    int i = blockIdx.x * blockDim.x + threadIdx.x;
    if (i < NPOS * DIM) g_acc[i] = 0.f;
    if (i < NPOS) { g_best[i] = 0ull; g_cnt[i] = 0.f; g_vis[i] = 0.f; }
}

__global__ void k_vis(const int* __restrict__ visible) {
    int i = blockIdx.x * blockDim.x + threadIdx.x;
    if (i < NVIS) g_vis[visible[i]] = 1.0f;
}

// C[8192,24576] = X[:8192] @ Mem^T   (3xTF32 split) + fused argmax of scores
__global__ void __launch_bounds__(128) k_gemm(const float* __restrict__ X,
                                              const float* __restrict__ Mem,
                                              const int*   __restrict__ Y,
                                              float* __restrict__ outSim)
{
    extern __shared__ float sm[];
    float* As = sm;          // packed: [8 mt][8 ks][32 lanes][4 regs]  (8192 floats)
    float* Bs = sm + 8192;   // packed: [16 nt][8 ks][32 lanes][2 regs] (8192 floats)

    const int bn  = blockIdx.x;   // 0..191
    const int bm  = blockIdx.y;   // 0..63
    const int tid = threadIdx.x;

    const float* Ag = X   + (size_t)bm * BM * DIM;
    const float* Bg = Mem + (size_t)bn * BN * DIM;

    // --- load A (coalesced float4 from gmem, scatter to packed smem) ---
    for (int q = tid; q < BM * DIM / 4; q += 128) {
        int r  = q >> 4;          // row in tile
        int kq = q & 15;          // float4 index along K
        float4 v = reinterpret_cast<const float4*>(Ag)[q];
        int mt = r >> 4, rr = r & 15;
        int g = rr & 7, ah = rr >> 3;
        const float* vp = reinterpret_cast<const float*>(&v);
        #pragma unroll
        for (int j = 0; j < 4; j++) {
            int k  = kq * 4 + j;
            int ks = k >> 3, kk = k & 7;
            int c  = kk & 3, ch = kk >> 2;
            As[(((mt * 8 + ks) * 32) + g * 4 + c) * 4 + (ah + 2 * ch)] = vp[j];
        }
    }
    // --- load B ---
    for (int q = tid; q < BN * DIM / 4; q += 128) {
        int n  = q >> 4;
        int kq = q & 15;
        float4 v = reinterpret_cast<const float4*>(Bg)[q];
        int nt = n >> 3, g = n & 7;
        const float* vp = reinterpret_cast<const float*>(&v);
        #pragma unroll
        for (int j = 0; j < 4; j++) {
            int k  = kq * 4 + j;
            int ks = k >> 3, kk = k & 7;
            int c  = kk & 3, ch = kk >> 2;
            Bs[(((nt * 8 + ks) * 32) + g * 4 + c) * 2 + ch] = vp[j];
        }
    }
    __syncthreads();

    const int w    = tid >> 5;
    const int wm   = w >> 1;        // 0..1
    const int wn   = w & 1;         // 0..1
    const int lane = tid & 31;

    float c[4][8][4];
    #pragma unroll
    for (int i = 0; i < 4; i++)
        #pragma unroll
        for (int j = 0; j < 8; j++)
            #pragma unroll
            for (int k = 0; k < 4; k++) c[i][j][k] = 0.f;

    const float4* As4 = reinterpret_cast<const float4*>(As);
    const float2* Bs2 = reinterpret_cast<const float2*>(Bs);

    #pragma unroll 1
    for (int ks = 0; ks < 8; ks++) {
        unsigned int ahi[4][4], alo[4][4];
        #pragma unroll
        for (int mt = 0; mt < 4; mt++) {
            float4 a = As4[((wm * 4 + mt) * 8 + ks) * 32 + lane];
            split_tf32(a.x, ahi[mt][0], alo[mt][0]);
            split_tf32(a.y, ahi[mt][1], alo[mt][1]);
            split_tf32(a.z, ahi[mt][2], alo[mt][2]);
            split_tf32(a.w, ahi[mt][3], alo[mt][3]);
        }
        unsigned int bhi[8][2], blo[8][2];
        #pragma unroll
        for (int nt = 0; nt < 8; nt++) {
            float2 b = Bs2[((wn * 8 + nt) * 8 + ks) * 32 + lane];
            split_tf32(b.x, bhi[nt][0], blo[nt][0]);
            split_tf32(b.y, bhi[nt][1], blo[nt][1]);
        }
        #pragma unroll
        for (int mt = 0; mt < 4; mt++)
            #pragma unroll
            for (int nt = 0; nt < 8; nt++) {
                mma_tf32(c[mt][nt], alo[mt], bhi[nt]);
                mma_tf32(c[mt][nt], ahi[mt], blo[nt]);
                mma_tf32(c[mt][nt], ahi[mt], bhi[nt]);
            }
    }

    // --- epilogue: store + fused argmax over score region (cols < NPOS) ---
    const int cRow = bm * BM + wm * 64;
    const int cCol = bn * BN + wn * 64;
    const int g    = lane >> 2;
    const int cc   = lane & 3;
    const bool doArg = (bn < (NPOS / BN));

    int yv0[4], yv1[4];
    if (doArg) {
        #pragma unroll
        for (int mt = 0; mt < 4; mt++) {
            yv0[mt] = Y[cRow + mt * 16 + g];
            yv1[mt] = Y[cRow + mt * 16 + g + 8];
        }
    }
    unsigned long long best[4][2];
    #pragma unroll
    for (int i = 0; i < 4; i++) { best[i][0] = 0ull; best[i][1] = 0ull; }

    #pragma unroll
    for (int mt = 0; mt < 4; mt++) {
        int r0 = cRow + mt * 16 + g;
        #pragma unroll
        for (int nt = 0; nt < 8; nt++) {
            int col0 = cCol + nt * 8 + cc * 2;
            float2 v01 = make_float2(c[mt][nt][0], c[mt][nt][1]);
            float2 v23 = make_float2(c[mt][nt][2], c[mt][nt][3]);
            *reinterpret_cast<float2*>(&outSim[(size_t)r0 * MMEM + col0])       = v01;
            *reinterpret_cast<float2*>(&outSim[(size_t)(r0 + 8) * MMEM + col0]) = v23;
            if (doArg) {
                float s0 = v01.x + ((col0     == yv0[mt]) ? 2.0f : 0.0f);
                float s1 = v01.y + ((col0 + 1 == yv0[mt]) ? 2.0f : 0.0f);
                float s2 = v23.x + ((col0     == yv1[mt]) ? 2.0f : 0.0f);
                float s3 = v23.y + ((col0 + 1 == yv1[mt]) ? 2.0f : 0.0f);
                unsigned long long p;
                p = packv(s0, col0);     if (p > best[mt][0]) best[mt][0] = p;
                p = packv(s1, col0 + 1); if (p > best[mt][0]) best[mt][0] = p;
                p = packv(s2, col0);     if (p > best[mt][1]) best[mt][1] = p;
                p = packv(s3, col0 + 1); if (p > best[mt][1]) best[mt][1] = p;
            }
        }
    }
    if (doArg) {
        #pragma unroll
        for (int mt = 0; mt < 4; mt++) {
            #pragma unroll
            for (int h = 0; h < 2; h++) {
                unsigned long long b = best[mt][h];
                unsigned long long o;
                o = __shfl_xor_sync(0xFFFFFFFFu, b, 1); if (o > b) b = o;
                o = __shfl_xor_sync(0xFFFFFFFFu, b, 2); if (o > b) b = o;
                if (cc == 0) atomicMax(&g_best[cRow + mt * 16 + h * 8 + g], b);
            }
        }
    }
}

// per-row: finalize y_idx, accumulate segment sums
__global__ void k_post(const float* __restrict__ X, float* __restrict__ outY) {
    int warp = (blockIdx.x * blockDim.x + threadIdx.x) >> 5;
    int lane = threadIdx.x & 31;
    if (warp >= NPOS) return;
    unsigned int low = (unsigned int)(g_best[warp] & 0xFFFFFFFFull);
    int idx = (int)(0xFFFFFFFFu - low);
    if (lane == 0) {
        outY[warp] = (float)idx;
        atomicAdd(&g_cnt[idx], 1.0f);
    }
    atomicAdd(&g_acc[idx * DIM + lane],      X[warp * DIM + lane]);
    atomicAdd(&g_acc[idx * DIM + lane + 32], X[warp * DIM + lane + 32]);
}

// build new_memory
__global__ void k_mem(const float* __restrict__ X, const float* __restrict__ Mem,
                      const float* __restrict__ params, float* __restrict__ outMem) {
    int warp = (blockIdx.x * blockDim.x + threadIdx.x) >> 5;
    int lane = threadIdx.x & 31;
    if (warp >= MMEM) return;
    int r = warp;
    float o0, o1;
    if (r < NPOS) {
        float mom = params[3];
        float cnt = g_cnt[r];
        float vis = g_vis[r];
        float valid = (cnt > 0.1f) ? vis : 0.0f;
        float m0 = Mem[r * DIM + lane];
        float m1 = Mem[r * DIM + lane + 32];
        float inv_c = 1.0f / (cnt + 1e-8f);
        float g0 = g_acc[r * DIM + lane] * inv_c;
        float g1 = g_acc[r * DIM + lane + 32] * inv_c;
        float blend = valid * mom + 1.0f - valid;
        float gw = (1.0f - mom) * valid;
        o0 = m0 * blend + g0 * gw;
        o1 = m1 * blend + g1 * gw;
        float ss = o0 * o0 + o1 * o1;
        #pragma unroll
        for (int s = 16; s; s >>= 1) ss += __shfl_xor_sync(0xFFFFFFFFu, ss, s);
        float inv = 1.0f / fmaxf(sqrtf(ss), 1e-12f);
        o0 *= inv; o1 *= inv;
    } else if (r < NPOS + NNEG) {          // 8192..12287: unchanged
        o0 = Mem[r * DIM + lane];
        o1 = Mem[r * DIM + lane + 32];
    } else if (r < NPOS + 2 * NNEG) {      // 12288..16383: x[n_pos:]  (lru=1)
        o0 = X[(size_t)(r - NNEG) * DIM + lane];
        o1 = X[(size_t)(r - NNEG) * DIM + lane + 32];
    } else {                               // unchanged
        o0 = Mem[r * DIM + lane];
        o1 = Mem[r * DIM + lane + 32];
    }
    outMem[r * DIM + lane]      = o0;
    outMem[r * DIM + lane + 32] = o1;
}

// ---------------- launch ----------------
extern "C" void kernel_launch(void* const* d_in, const int* in_sizes, int n_in,
                              void* d_out, int out_size) {
    const float* x = nullptr; const int* y = nullptr; const int* visible = nullptr;
    const float* mem = nullptr; const float* params = nullptr;
    for (int i = 0; i < n_in; i++) {
        switch (in_sizes[i]) {
            case NX * DIM:   x       = (const float*)d_in[i]; break;
            case NPOS:       y       = (const int*)  d_in[i]; break;
            case NVIS:       visible = (const int*)  d_in[i]; break;
            case MMEM * DIM: mem     = (const float*)d_in[i]; break;
            case 4:          params  = (const float*)d_in[i]; break;
            default: break;
        }
    }
    float* outSim = (float*)d_out;
    float* outY   = outSim + (size_t)NPOS * MMEM;
    float* outMem = outY + NPOS;

    (void)cudaFuncSetAttribute(k_gemm, cudaFuncAttributeMaxDynamicSharedMemorySize, 65536);

    k_init<<<(NPOS * DIM + 255) / 256, 256>>>();
    k_vis<<<(NVIS + 255) / 256, 256>>>(visible);
    dim3 grid(MMEM / BN, NPOS / BM);
    k_gemm<<<grid, 128, 65536>>>(x, mem, y, outSim);
    k_post<<<(NPOS * 32 + 255) / 256, 256>>>(x, outY);
    k_mem<<<(MMEM * 32 + 255) / 256, 256>>>(x, mem, params, outMem);
}

// round 8
// speedup vs baseline: 1.4432x; 1.4432x over previous
#include <cuda_runtime.h>
#include <cstdint>

#define NPOS  8192
#define NNEG  4096
#define NVIS  4096
#define DIM   64
#define MMEM  24576   // NPOS + 4*NNEG
#define NX    12288   // NPOS + NNEG

#define NT     8      // tiles (128 cols) per strip
#define NSTRIP 24     // strips of 1024 cols

// smem layout (bytes)
#define SM_AS   0              // A frag layout, 32KB
#define SM_BS   32768          // B frag layout, 32KB
#define SM_RAW  65536          // raw staging (128 x 68 floats = 34816B); aliased as epilogue scratch
#define SM_TOTAL (65536 + 34816)

// ---------------- device scratch ----------------
__device__ unsigned long long g_best[NPOS];
__device__ float g_cnt[NPOS];
__device__ float g_vis[NPOS];
__device__ float g_acc[NPOS * DIM];

// ---------------- helpers ----------------
__device__ __forceinline__ uint32_t smem_u32(const void* p) {
    uint32_t a;
    asm("{ .reg .u64 t; cvta.to.shared.u64 t, %1; cvt.u32.u64 %0, t; }" : "=r"(a) : "l"(p));
    return a;
}
__device__ __forceinline__ unsigned long long packv(float v, int col) {
    unsigned int u = __float_as_uint(v);
    u = (u & 0x80000000u) ? ~u : (u | 0x80000000u);   // monotone sortable key
    return ((unsigned long long)u << 32) | (unsigned int)(0xFFFFFFFFu - (unsigned int)col);
}
__device__ __forceinline__ void mma_tf32(float c[4], const unsigned int a[4], const unsigned int b[2]) {
    asm volatile(
        "mma.sync.aligned.m16n8k8.row.col.f32.tf32.tf32.f32 "
        "{%0,%1,%2,%3}, {%4,%5,%6,%7}, {%8,%9}, {%0,%1,%2,%3};\n"
        : "+f"(c[0]), "+f"(c[1]), "+f"(c[2]), "+f"(c[3])
        : "r"(a[0]), "r"(a[1]), "r"(a[2]), "r"(a[3]), "r"(b[0]), "r"(b[1]));
}
__device__ __forceinline__ void splitu(float x, unsigned int &hi, unsigned int &lo) {
    unsigned int hb = __float_as_uint(x) & 0xFFFFE000u;   // exact tf32 split
    hi = hb;
    lo = __float_as_uint(x - __uint_as_float(hb));
}

// ---------------- small kernels ----------------
__global__ void k_init() {
    int i = blockIdx.x * blockDim.x + threadIdx.x;
    if (i < NPOS * DIM) g_acc[i] = 0.f;
    if (i < NPOS) { g_best[i] = 0ull; g_cnt[i] = 0.f; g_vis[i] = 0.f; }
}
__global__ void k_vis(const int* __restrict__ visible) {
    int i = blockIdx.x * blockDim.x + threadIdx.x;
    if (i < NVIS) g_vis[visible[i]] = 1.0f;
}

// ---------------- main GEMM: C = X[:8192] @ Mem^T (3xTF32) + fused argmax ----------------
__global__ void __launch_bounds__(256, 2)
k_gemm(const float* __restrict__ X, const float* __restrict__ Mem,
       const int* __restrict__ Y, float* __restrict__ outSim)
{
    extern __shared__ char smem[];
    float4* As4 = reinterpret_cast<float4*>(smem + SM_AS);
    float4* Bs4 = reinterpret_cast<float4*>(smem + SM_BS);
    float*  raw = reinterpret_cast<float*>(smem + SM_RAW);
    const uint32_t rawb = smem_u32(raw);

    const int tid  = threadIdx.x;
    const int wid  = tid >> 5;
    const int lane = tid & 31;
    const int wm   = wid >> 1;       // 0..3 : 32-row slice
    const int wn   = wid & 1;        // 0..1 : 64-col slice
    const int g    = lane >> 2;      // frag row group 0..7
    const int cc   = lane & 3;       // frag col group 0..3

    const int ctaM0 = blockIdx.y * 128;
    const int S0    = blockIdx.x * 1024;
    const bool doArg = (blockIdx.x < 8);     // strip cols < NPOS

    // ---- stage + convert A (once per CTA) ----
    {
        const float* Ag = X + (size_t)ctaM0 * DIM;
        #pragma unroll
        for (int i = 0; i < 8; i++) {
            int q = tid + i * 256; int row = q >> 4, kq = q & 15;
            asm volatile("cp.async.cg.shared.global [%0], [%1], 16;"
                         :: "r"(rawb + (uint32_t)(row * 68 + kq * 4) * 4u),
                            "l"(Ag + row * 64 + kq * 4));
        }
        asm volatile("cp.async.commit_group;");
        asm volatile("cp.async.wait_group 0;");
        __syncthreads();
        #pragma unroll
        for (int i = 0; i < 8; i++) {
            int L = tid + i * 256;
            int c = L & 3, gq = (L >> 2) & 7, ks = (L >> 5) & 7, blk = L >> 8;
            int me = blk * 16 + gq, k0 = ks * 8 + c;
            float4 v;
            v.x = raw[me * 68 + k0];       v.y = raw[(me + 8) * 68 + k0];
            v.z = raw[me * 68 + k0 + 4];   v.w = raw[(me + 8) * 68 + k0 + 4];
            As4[L] = v;                     // A cell: {m,k0},{m+8,k0},{m,k0+4},{m+8,k0+4}
        }
    }

    // per-lane argmax state (4 row slots: mt x h)
    float bv[2][2]; int bc[2][2]; int yv[2][2];
    if (doArg) {
        #pragma unroll
        for (int mt = 0; mt < 2; mt++)
            #pragma unroll
            for (int h = 0; h < 2; h++) {
                yv[mt][h] = Y[ctaM0 + wm * 32 + mt * 16 + h * 8 + g];
                bv[mt][h] = -1e30f; bc[mt][h] = 0;
            }
    }

    for (int t = 0; t < NT; t++) {
        __syncthreads();   // prior epilogue scratch reads & MMA Bs reads done

        // ---- stage B(t) raw ----
        const float* Bg = Mem + (size_t)(S0 + t * 128) * DIM;
        #pragma unroll
        for (int i = 0; i < 8; i++) {
            int q = tid + i * 256; int row = q >> 4, kq = q & 15;
            asm volatile("cp.async.cg.shared.global [%0], [%1], 16;"
                         :: "r"(rawb + (uint32_t)(row * 68 + kq * 4) * 4u),
                            "l"(Bg + row * 64 + kq * 4));
        }
        asm volatile("cp.async.commit_group;");
        asm volatile("cp.async.wait_group 0;");
        __syncthreads();

        // ---- convert raw -> B frag layout (conflict-free LDS, coalesced STS.128) ----
        #pragma unroll
        for (int i = 0; i < 8; i++) {
            int L = tid + i * 256;
            int c = L & 3, gq = (L >> 2) & 7, ks = (L >> 5) & 7, blk = L >> 8;
            int ne = blk * 16 + gq, k0 = ks * 8 + c;
            float4 v;
            v.x = raw[ne * 68 + k0];       v.y = raw[ne * 68 + k0 + 4];
            v.z = raw[(ne + 8) * 68 + k0]; v.w = raw[(ne + 8) * 68 + k0 + 4];
            Bs4[L] = v;                     // B cell: {n,k0},{n,k0+4},{n+8,k0},{n+8,k0+4}
        }
        __syncthreads();

        // ---- MMA: 32x128 per warp (acc over 8 nt) ----
        float acc[2][8][4];
        #pragma unroll
        for (int a = 0; a < 2; a++)
            #pragma unroll
            for (int b = 0; b < 8; b++)
                #pragma unroll
                for (int k = 0; k < 4; k++) acc[a][b][k] = 0.f;

        #pragma unroll 2
        for (int ks = 0; ks < 8; ks++) {
            unsigned int ahi[2][4], alo[2][4];
            #pragma unroll
            for (int mt = 0; mt < 2; mt++) {
                float4 a = As4[(wm * 2 + mt) * 256 + ks * 32 + lane];
                splitu(a.x, ahi[mt][0], alo[mt][0]);
                splitu(a.y, ahi[mt][1], alo[mt][1]);
                splitu(a.z, ahi[mt][2], alo[mt][2]);
                splitu(a.w, ahi[mt][3], alo[mt][3]);
            }
            #pragma unroll
            for (int nt2 = 0; nt2 < 4; nt2++) {
                float4 b = Bs4[(wn * 4 + nt2) * 256 + ks * 32 + lane];
                unsigned int bh0[2], bl0[2], bh1[2], bl1[2];
                splitu(b.x, bh0[0], bl0[0]); splitu(b.y, bh0[1], bl0[1]);
                splitu(b.z, bh1[0], bl1[0]); splitu(b.w, bh1[1], bl1[1]);
                #pragma unroll
                for (int mt = 0; mt < 2; mt++) {
                    mma_tf32(acc[mt][2 * nt2],     alo[mt], bh0);
                    mma_tf32(acc[mt][2 * nt2],     ahi[mt], bl0);
                    mma_tf32(acc[mt][2 * nt2],     ahi[mt], bh0);
                    mma_tf32(acc[mt][2 * nt2 + 1], alo[mt], bh1);
                    mma_tf32(acc[mt][2 * nt2 + 1], ahi[mt], bl1);
                    mma_tf32(acc[mt][2 * nt2 + 1], ahi[mt], bh1);
                }
            }
        }

        // ---- epilogue: argmax + swizzled transpose + coalesced STG ----
        const int colw = S0 + t * 128 + wn * 64;
        float* scr = raw + wid * 1024;    // per-warp 4KB slice of raw region
        #pragma unroll
        for (int mt = 0; mt < 2; mt++) {
            if (doArg) {
                #pragma unroll
                for (int nt = 0; nt < 8; nt++) {
                    int colb = colw + nt * 8 + cc * 2;
                    #pragma unroll
                    for (int h = 0; h < 2; h++) {
                        float s0 = acc[mt][nt][h * 2]     + ((colb     == yv[mt][h]) ? 2.0f : 0.0f);
                        float s1 = acc[mt][nt][h * 2 + 1] + ((colb + 1 == yv[mt][h]) ? 2.0f : 0.0f);
                        if (s0 > bv[mt][h]) { bv[mt][h] = s0; bc[mt][h] = colb; }
                        if (s1 > bv[mt][h]) { bv[mt][h] = s1; bc[mt][h] = colb + 1; }
                    }
                }
            }
            // scatter accums into swizzled scratch (16 rows x 64 cols)
            #pragma unroll
            for (int nt = 0; nt < 8; nt++) {
                #pragma unroll
                for (int h = 0; h < 2; h++) {
                    int r  = g + h * 8;
                    int cs = (2 * nt + (cc >> 1)) ^ (g << 1);
                    float2 v = make_float2(acc[mt][nt][h * 2], acc[mt][nt][h * 2 + 1]);
                    *reinterpret_cast<float2*>(scr + r * 64 + cs * 4 + (cc & 1) * 2) = v;
                }
            }
            __syncwarp();
            float* orow = outSim + (size_t)(ctaM0 + wm * 32 + mt * 16) * MMEM + colw;
            #pragma unroll
            for (int i2 = 0; i2 < 8; i2++) {
                int r  = i2 * 2 + (lane >> 4);
                int ci = lane & 15;
                int cs = ci ^ ((r & 7) << 1);
                float4 v = *reinterpret_cast<float4*>(scr + r * 64 + cs * 4);
                *reinterpret_cast<float4*>(orow + (size_t)r * MMEM + ci * 4) = v;
            }
            __syncwarp();
        }
    }

    // ---- strip-level argmax commit ----
    if (doArg) {
        #pragma unroll
        for (int mt = 0; mt < 2; mt++)
            #pragma unroll
            for (int h = 0; h < 2; h++) {
                unsigned long long p = packv(bv[mt][h], bc[mt][h]);
                unsigned long long o;
                o = __shfl_xor_sync(0xFFFFFFFFu, p, 1); if (o > p) p = o;
                o = __shfl_xor_sync(0xFFFFFFFFu, p, 2); if (o > p) p = o;
                if (cc == 0) atomicMax(&g_best[ctaM0 + wm * 32 + mt * 16 + h * 8 + g], p);
            }
    }
}

// ---------------- post kernels ----------------
__global__ void k_post(const float* __restrict__ X, float* __restrict__ outY) {
    int warp = (blockIdx.x * blockDim.x + threadIdx.x) >> 5;
    int lane = threadIdx.x & 31;
    if (warp >= NPOS) return;
    unsigned int low = (unsigned int)(g_best[warp] & 0xFFFFFFFFull);
    int idx = (int)(0xFFFFFFFFu - low);
    if (lane == 0) {
        outY[warp] = (float)idx;
        atomicAdd(&g_cnt[idx], 1.0f);
    }
    atomicAdd(&g_acc[idx * DIM + lane],      X[warp * DIM + lane]);
    atomicAdd(&g_acc[idx * DIM + lane + 32], X[warp * DIM + lane + 32]);
}

__global__ void k_mem(const float* __restrict__ X, const float* __restrict__ Mem,
                      const float* __restrict__ params, float* __restrict__ outMem) {
    int warp = (blockIdx.x * blockDim.x + threadIdx.x) >> 5;
    int lane = threadIdx.x & 31;
    if (warp >= MMEM) return;
    int r = warp;
    float o0, o1;
    if (r < NPOS) {
        float mom = params[3];
        float cnt = g_cnt[r];
        float vis = g_vis[r];
        float valid = (cnt > 0.1f) ? vis : 0.0f;
        float m0 = Mem[r * DIM + lane];
        float m1 = Mem[r * DIM + lane + 32];
        float inv_c = 1.0f / (cnt + 1e-8f);
        float g0 = g_acc[r * DIM + lane] * inv_c;
        float g1 = g_acc[r * DIM + lane + 32] * inv_c;
        float blend = valid * mom + 1.0f - valid;
        float gw = (1.0f - mom) * valid;
        o0 = m0 * blend + g0 * gw;
        o1 = m1 * blend + g1 * gw;
        float ss = o0 * o0 + o1 * o1;
        #pragma unroll
        for (int s = 16; s; s >>= 1) ss += __shfl_xor_sync(0xFFFFFFFFu, ss, s);
        float inv = 1.0f / fmaxf(sqrtf(ss), 1e-12f);
        o0 *= inv; o1 *= inv;
    } else if (r < NPOS + NNEG) {
        o0 = Mem[r * DIM + lane];
        o1 = Mem[r * DIM + lane + 32];
    } else if (r < NPOS + 2 * NNEG) {      // lru=1 slot gets x[n_pos:]
        o0 = X[(size_t)(r - NNEG) * DIM + lane];
        o1 = X[(size_t)(r - NNEG) * DIM + lane + 32];
    } else {
        o0 = Mem[r * DIM + lane];
        o1 = Mem[r * DIM + lane + 32];
    }
    outMem[r * DIM + lane]      = o0;
    outMem[r * DIM + lane + 32] = o1;
}

// ---------------- launch ----------------
extern "C" void kernel_launch(void* const* d_in, const int* in_sizes, int n_in,
                              void* d_out, int out_size) {
    const float* x = nullptr; const int* y = nullptr; const int* visible = nullptr;
    const float* mem = nullptr; const float* params = nullptr;
    for (int i = 0; i < n_in; i++) {
        switch (in_sizes[i]) {
            case NX * DIM:   x       = (const float*)d_in[i]; break;
            case NPOS:       y       = (const int*)  d_in[i]; break;
            case NVIS:       visible = (const int*)  d_in[i]; break;
            case MMEM * DIM: mem     = (const float*)d_in[i]; break;
            case 4:          params  = (const float*)d_in[i]; break;
            default: break;
        }
    }
    float* outSim = (float*)d_out;
    float* outY   = outSim + (size_t)NPOS * MMEM;
    float* outMem = outY + NPOS;

    (void)cudaFuncSetAttribute(k_gemm, cudaFuncAttributeMaxDynamicSharedMemorySize, SM_TOTAL);

    k_init<<<(NPOS * DIM + 255) / 256, 256>>>();
    k_vis<<<(NVIS + 255) / 256, 256>>>(visible);
    dim3 grid(NSTRIP, NPOS / 128);
    k_gemm<<<grid, 256, SM_TOTAL>>>(x, mem, y, outSim);
    k_post<<<(NPOS * 32 + 255) / 256, 256>>>(x, outY);
    k_mem<<<(MMEM * 32 + 255) / 256, 256>>>(x, mem, params, outMem);
}

// round 10
// speedup vs baseline: 1.5664x; 1.0854x over previous
#include <cuda_runtime.h>
#include <cstdint>

#define NPOS  8192
#define NNEG  4096
#define NVIS  4096
#define DIM   64
#define MMEM  24576   // NPOS + 4*NNEG
#define NX    12288   // NPOS + NNEG

#define NT     8      // tiles (128 cols) per strip
#define NSTRIP 24     // strips of 1024 cols

// smem layout (bytes)
#define SM_AS   0              // A frag layout, 32KB
#define SM_B0   32768          // B buffer 0 (raw-swizzled then frag, in place), 32KB
#define SM_B1   65536          // B buffer 1, 32KB
#define SM_SCR  98304          // epilogue scratch: 8 warps x 2KB
#define SM_TOTAL (98304 + 16384)   // 114688 -> 2 CTAs/SM

// ---------------- device scratch (zero-init; every launch leaves them zeroed) ----------------
__device__ unsigned long long g_best[NPOS];
__device__ float g_cnt[NPOS];
__device__ float g_vis[NPOS];
__device__ float g_acc[NPOS * DIM];

// ---------------- helpers ----------------
__device__ __forceinline__ uint32_t smem_u32(const void* p) {
    uint32_t a;
    asm("{ .reg .u64 t; cvta.to.shared.u64 t, %1; cvt.u32.u64 %0, t; }" : "=r"(a) : "l"(p));
    return a;
}
__device__ __forceinline__ unsigned long long packv(float v, int col) {
    unsigned int u = __float_as_uint(v);
    u = (u & 0x80000000u) ? ~u : (u | 0x80000000u);   // monotone sortable key
    return ((unsigned long long)u << 32) | (unsigned int)(0xFFFFFFFFu - (unsigned int)col);
}
__device__ __forceinline__ void mma_tf32(float c[4], const unsigned int a[4], const unsigned int b[2]) {
    asm volatile(
        "mma.sync.aligned.m16n8k8.row.col.f32.tf32.tf32.f32 "
        "{%0,%1,%2,%3}, {%4,%5,%6,%7}, {%8,%9}, {%0,%1,%2,%3};\n"
        : "+f"(c[0]), "+f"(c[1]), "+f"(c[2]), "+f"(c[3])
        : "r"(a[0]), "r"(a[1]), "r"(a[2]), "r"(a[3]), "r"(b[0]), "r"(b[1]));
}
__device__ __forceinline__ void splitu(float x, unsigned int &hi, unsigned int &lo) {
    unsigned int hb = __float_as_uint(x) & 0xFFFFE000u;   // exact tf32 split
    hi = hb;
    lo = __float_as_uint(x - __uint_as_float(hb));
}
// swizzled raw staging: element (row, k) -> byte offset
//   granule(16B) = row*16 + ((k>>2) ^ (row & 15)); word = k & 3
__device__ __forceinline__ uint32_t sroff(int row, int kgran) {
    return (uint32_t)((row * 16 + (kgran ^ (row & 15))) << 4);
}

// ---------------- small kernels ----------------
__global__ void k_vis(const int* __restrict__ visible) {
    int i = blockIdx.x * blockDim.x + threadIdx.x;
    if (i < NVIS) g_vis[visible[i]] = 1.0f;
}

// ---------------- main GEMM: C = X[:8192] @ Mem^T (3xTF32) + fused argmax ----------------
__global__ void __launch_bounds__(256, 2)
k_gemm(const float* __restrict__ X, const float* __restrict__ Mem,
       const int* __restrict__ Y, float* __restrict__ outSim)
{
    extern __shared__ char smem[];
    float4* As4 = reinterpret_cast<float4*>(smem + SM_AS);

    const int tid  = threadIdx.x;
    const int wid  = tid >> 5;
    const int lane = tid & 31;
    const int wm   = wid >> 1;       // 0..3 : 32-row slice
    const int wn   = wid & 1;        // 0..1 : 64-col slice
    const int g    = lane >> 2;      // frag row group 0..7
    const int cc   = lane & 3;       // frag col group 0..3

    const int ctaM0 = blockIdx.y * 128;
    const int S0    = blockIdx.x * 1024;
    const bool doArg = (blockIdx.x < 8);     // strip cols < NPOS

    // decomposition of linear cell id used by stage/convert
    const int l_c  = tid & 3;
    const int l_gq = (tid >> 2) & 7;
    const int l_ks = (tid >> 5) & 7;         // constant within a warp

    // ---- prologue: stage A (into B1 region) + prefetch B(0) (into B0) ----
    {
        const float* Ag = X + (size_t)ctaM0 * DIM;
        const uint32_t b1 = smem_u32(smem + SM_B1);
        #pragma unroll
        for (int i = 0; i < 8; i++) {
            int q = tid + i * 256; int row = q >> 4, kq = q & 15;
            asm volatile("cp.async.cg.shared.global [%0], [%1], 16;"
                         :: "r"(b1 + sroff(row, kq)), "l"(Ag + row * 64 + kq * 4));
        }
        asm volatile("cp.async.commit_group;");
        const float* Bg = Mem + (size_t)S0 * DIM;
        const uint32_t b0 = smem_u32(smem + SM_B0);
        #pragma unroll
        for (int i = 0; i < 8; i++) {
            int q = tid + i * 256; int row = q >> 4, kq = q & 15;
            asm volatile("cp.async.cg.shared.global [%0], [%1], 16;"
                         :: "r"(b0 + sroff(row, kq)), "l"(Bg + row * 64 + kq * 4));
        }
        asm volatile("cp.async.commit_group;");
        asm volatile("cp.async.wait_group 1;");   // A staged
        __syncthreads();
        // convert A: B1(swizzled raw) -> As (frag layout); A cell {m,k0},{m+8,k0},{m,k0+4},{m+8,k0+4}
        #pragma unroll
        for (int i = 0; i < 8; i++) {
            int L = tid + i * 256;
            int blk = L >> 8;
            int me = blk * 16 + l_gq;
            float4 v;
            v.x = *reinterpret_cast<float*>(smem + SM_B1 + sroff(me,     2 * l_ks)     + l_c * 4);
            v.y = *reinterpret_cast<float*>(smem + SM_B1 + sroff(me + 8, 2 * l_ks)     + l_c * 4);
            v.z = *reinterpret_cast<float*>(smem + SM_B1 + sroff(me,     2 * l_ks + 1) + l_c * 4);
            v.w = *reinterpret_cast<float*>(smem + SM_B1 + sroff(me + 8, 2 * l_ks + 1) + l_c * 4);
            As4[L] = v;
        }
        // no sync needed here: loop-top sync orders As writes before MMA reads
    }

    // per-lane argmax state (4 row slots: mt x h)
    float bv[2][2]; int bc[2][2]; int yv[2][2];
    if (doArg) {
        #pragma unroll
        for (int mt = 0; mt < 2; mt++)
            #pragma unroll
            for (int h = 0; h < 2; h++) {
                yv[mt][h] = Y[ctaM0 + wm * 32 + mt * 16 + h * 8 + g];
                bv[mt][h] = -1e30f; bc[mt][h] = 0;
            }
    }

    float* scr = reinterpret_cast<float*>(smem + SM_SCR) + wid * 512;  // 2KB per warp

    for (int t = 0; t < NT; t++) {
        char* bb = smem + (((t & 1) == 0) ? SM_B0 : SM_B1);
        float4* Bs4 = reinterpret_cast<float4*>(bb);

        asm volatile("cp.async.wait_group 0;");   // raw(t) complete (this thread)
        __syncthreads();                          // visible to all; all warps done with iter t-1

        // prefetch B(t+1) into the other buffer (its reads from iter t-1 are done)
        if (t + 1 < NT) {
            const float* Bg = Mem + (size_t)(S0 + (t + 1) * 128) * DIM;
            const uint32_t nb = smem_u32(smem + (((t & 1) == 0) ? SM_B1 : SM_B0));
            #pragma unroll
            for (int i = 0; i < 8; i++) {
                int q = tid + i * 256; int row = q >> 4, kq = q & 15;
                asm volatile("cp.async.cg.shared.global [%0], [%1], 16;"
                             :: "r"(nb + sroff(row, kq)), "l"(Bg + row * 64 + kq * 4));
            }
            asm volatile("cp.async.commit_group;");
        }

        // ---- in-place convert raw(t) -> frag layout ----
        {
            float4 v[8];
            #pragma unroll
            for (int i = 0; i < 8; i++) {
                int L = tid + i * 256;
                int blk = L >> 8;
                int ne = blk * 16 + l_gq;
                // B cell {n,k0},{n,k0+4},{n+8,k0},{n+8,k0+4}
                v[i].x = *reinterpret_cast<float*>(bb + sroff(ne,     2 * l_ks)     + l_c * 4);
                v[i].y = *reinterpret_cast<float*>(bb + sroff(ne,     2 * l_ks + 1) + l_c * 4);
                v[i].z = *reinterpret_cast<float*>(bb + sroff(ne + 8, 2 * l_ks)     + l_c * 4);
                v[i].w = *reinterpret_cast<float*>(bb + sroff(ne + 8, 2 * l_ks + 1) + l_c * 4);
            }
            __syncthreads();
            #pragma unroll
            for (int i = 0; i < 8; i++) Bs4[tid + i * 256] = v[i];
        }
        __syncthreads();

        // ---- MMA: 32x128 per warp ----
        float acc[2][8][4];
        #pragma unroll
        for (int a = 0; a < 2; a++)
            #pragma unroll
            for (int b = 0; b < 8; b++)
                #pragma unroll
                for (int k = 0; k < 4; k++) acc[a][b][k] = 0.f;

        #pragma unroll 2
        for (int ks = 0; ks < 8; ks++) {
            unsigned int ahi[2][4], alo[2][4];
            #pragma unroll
            for (int mt = 0; mt < 2; mt++) {
                float4 a = As4[(wm * 2 + mt) * 256 + ks * 32 + lane];
                splitu(a.x, ahi[mt][0], alo[mt][0]);
                splitu(a.y, ahi[mt][1], alo[mt][1]);
                splitu(a.z, ahi[mt][2], alo[mt][2]);
                splitu(a.w, ahi[mt][3], alo[mt][3]);
            }
            #pragma unroll
            for (int nt2 = 0; nt2 < 4; nt2++) {
                float4 b = Bs4[(wn * 4 + nt2) * 256 + ks * 32 + lane];
                unsigned int bh0[2], bl0[2], bh1[2], bl1[2];
                splitu(b.x, bh0[0], bl0[0]); splitu(b.y, bh0[1], bl0[1]);
                splitu(b.z, bh1[0], bl1[0]); splitu(b.w, bh1[1], bl1[1]);
                #pragma unroll
                for (int mt = 0; mt < 2; mt++) {
                    mma_tf32(acc[mt][2 * nt2],     alo[mt], bh0);
                    mma_tf32(acc[mt][2 * nt2],     ahi[mt], bl0);
                    mma_tf32(acc[mt][2 * nt2],     ahi[mt], bh0);
                    mma_tf32(acc[mt][2 * nt2 + 1], alo[mt], bh1);
                    mma_tf32(acc[mt][2 * nt2 + 1], ahi[mt], bl1);
                    mma_tf32(acc[mt][2 * nt2 + 1], ahi[mt], bh1);
                }
            }
        }

        // ---- epilogue: argmax + swizzled transpose (8-row halves) + coalesced STG ----
        const int colw = S0 + t * 128 + wn * 64;
        #pragma unroll
        for (int mt = 0; mt < 2; mt++) {
            if (doArg) {
                #pragma unroll
                for (int nt = 0; nt < 8; nt++) {
                    int colb = colw + nt * 8 + cc * 2;
                    #pragma unroll
                    for (int h = 0; h < 2; h++) {
                        float s0 = acc[mt][nt][h * 2]     + ((colb     == yv[mt][h]) ? 2.0f : 0.0f);
                        float s1 = acc[mt][nt][h * 2 + 1] + ((colb + 1 == yv[mt][h]) ? 2.0f : 0.0f);
                        if (s0 > bv[mt][h]) { bv[mt][h] = s0; bc[mt][h] = colb; }
                        if (s1 > bv[mt][h]) { bv[mt][h] = s1; bc[mt][h] = colb + 1; }
                    }
                }
            }
            #pragma unroll
            for (int p = 0; p < 2; p++) {       // 8-row half
                #pragma unroll
                for (int nt = 0; nt < 8; nt++) {
                    int cs = (2 * nt + (cc >> 1)) ^ (g << 1);
                    float2 v = make_float2(acc[mt][nt][p * 2], acc[mt][nt][p * 2 + 1]);
                    *reinterpret_cast<float2*>(scr + g * 64 + cs * 4 + (cc & 1) * 2) = v;
                }
                __syncwarp();
                float* orow = outSim + (size_t)(ctaM0 + wm * 32 + mt * 16 + p * 8) * MMEM + colw;
                #pragma unroll
                for (int i2 = 0; i2 < 4; i2++) {
                    int r  = i2 * 2 + (lane >> 4);
                    int ci = lane & 15;
                    int cs = ci ^ ((r & 7) << 1);
                    float4 v = *reinterpret_cast<float4*>(scr + r * 64 + cs * 4);
                    *reinterpret_cast<float4*>(orow + (size_t)r * MMEM + ci * 4) = v;
                }
                __syncwarp();
            }
        }
    }

    // ---- strip-level argmax commit ----
    if (doArg) {
        #pragma unroll
        for (int mt = 0; mt < 2; mt++)
            #pragma unroll
            for (int h = 0; h < 2; h++) {
                unsigned long long p = packv(bv[mt][h], bc[mt][h]);
                unsigned long long o;
                o = __shfl_xor_sync(0xFFFFFFFFu, p, 1); if (o > p) p = o;
                o = __shfl_xor_sync(0xFFFFFFFFu, p, 2); if (o > p) p = o;
                if (cc == 0) atomicMax(&g_best[ctaM0 + wm * 32 + mt * 16 + h * 8 + g], p);
            }
    }
}

// ---------------- post kernels (self-zeroing for graph replay) ----------------
__global__ void k_post(const float* __restrict__ X, float* __restrict__ outY) {
    int warp = (blockIdx.x * blockDim.x + threadIdx.x) >> 5;
    int lane = threadIdx.x & 31;
    if (warp >= NPOS) return;
    unsigned int low = (unsigned int)(g_best[warp] & 0xFFFFFFFFull);
    int idx = (int)(0xFFFFFFFFu - low);
    if (lane == 0) {
        g_best[warp] = 0ull;               // reset for next replay
        outY[warp] = (float)idx;
        atomicAdd(&g_cnt[idx], 1.0f);
    }
    atomicAdd(&g_acc[idx * DIM + lane],      X[warp * DIM + lane]);
    atomicAdd(&g_acc[idx * DIM + lane + 32], X[warp * DIM + lane + 32]);
}

__global__ void k_mem(const float* __restrict__ X, const float* __restrict__ Mem,
                      const float* __restrict__ params, float* __restrict__ outMem) {
    int warp = (blockIdx.x * blockDim.x + threadIdx.x) >> 5;
    int lane = threadIdx.x & 31;
    if (warp >= MMEM) return;
    int r = warp;
    float o0, o1;
    if (r < NPOS) {
        float mom = params[3];
        float cnt = g_cnt[r];
        float vis = g_vis[r];
        float valid = (cnt > 0.1f) ? vis : 0.0f;
        float m0 = Mem[r * DIM + lane];
        float m1 = Mem[r * DIM + lane + 32];
        float inv_c = 1.0f / (cnt + 1e-8f);
        float g0 = g_acc[r * DIM + lane] * inv_c;
        float g1 = g_acc[r * DIM + lane + 32] * inv_c;
        // reset scratch for next replay
        g_acc[r * DIM + lane] = 0.f;
        g_acc[r * DIM + lane + 32] = 0.f;
        if (lane == 0) { g_cnt[r] = 0.f; g_vis[r] = 0.f; }
        float blend = valid * mom + 1.0f - valid;
        float gw = (1.0f - mom) * valid;
        o0 = m0 * blend + g0 * gw;
        o1 = m1 * blend + g1 * gw;
        float ss = o0 * o0 + o1 * o1;
        #pragma unroll
        for (int s = 16; s; s >>= 1) ss += __shfl_xor_sync(0xFFFFFFFFu, ss, s);
        float inv = 1.0f / fmaxf(sqrtf(ss), 1e-12f);
        o0 *= inv; o1 *= inv;
    } else if (r < NPOS + NNEG) {
        o0 = Mem[r * DIM + lane];
        o1 = Mem[r * DIM + lane + 32];
    } else if (r < NPOS + 2 * NNEG) {      // lru=1 slot gets x[n_pos:]
        o0 = X[(size_t)(r - NNEG) * DIM + lane];
        o1 = X[(size_t)(r - NNEG) * DIM + lane + 32];
    } else {
        o0 = Mem[r * DIM + lane];
        o1 = Mem[r * DIM + lane + 32];
    }
    outMem[r * DIM + lane]      = o0;
    outMem[r * DIM + lane + 32] = o1;
}

// ---------------- launch ----------------
extern "C" void kernel_launch(void* const* d_in, const int* in_sizes, int n_in,
                              void* d_out, int out_size) {
    const float* x = nullptr; const int* y = nullptr; const int* visible = nullptr;
    const float* mem = nullptr; const float* params = nullptr;
    for (int i = 0; i < n_in; i++) {
        switch (in_sizes[i]) {
            case NX * DIM:   x       = (const float*)d_in[i]; break;
            case NPOS:       y       = (const int*)  d_in[i]; break;
            case NVIS:       visible = (const int*)  d_in[i]; break;
            case MMEM * DIM: mem     = (const float*)d_in[i]; break;
            case 4:          params  = (const float*)d_in[i]; break;
            default: break;
        }
    }
    float* outSim = (float*)d_out;
    float* outY   = outSim + (size_t)NPOS * MMEM;
    float* outMem = outY + NPOS;

    (void)cudaFuncSetAttribute(k_gemm, cudaFuncAttributeMaxDynamicSharedMemorySize, SM_TOTAL);

    k_vis<<<(NVIS + 255) / 256, 256>>>(visible);
    dim3 grid(NSTRIP, NPOS / 128);
    k_gemm<<<grid, 256, SM_TOTAL>>>(x, mem, y, outSim);
    k_post<<<(NPOS * 32 + 255) / 256, 256>>>(x, outY);
    k_mem<<<(MMEM * 32 + 255) / 256, 256>>>(x, mem, params, outMem);
}